// round 12
// baseline (speedup 1.0000x reference)
#include <cuda_runtime.h>
#include <cuda_bf16.h>
#include <cstdint>

// LSTM B=4096,T=512,IN=1,H=32,OUT=1 — bf16 m16n8k16 mma.sync, fp32 accum,
// fp32 cell state. R12: sigmoid gates (i,f,o) computed for the thread's TWO
// cells in ONE tanh.approx.f16x2 each (10 -> 7 MUFU per thread-step; MUFU is
// the binding pipe on critical SMs). g-gate and tanh(c) stay fp32 MUFU.
// 512 CTAs x 128 thr, NB=8; one bar.sync per step, h as bf16x2 in smem.

#define TT  512
#define HH  32
#define BB  4096
#define NB  8
#define XCH 64

typedef unsigned long long u64;

__device__ __forceinline__ uint32_t pack_bf16(float lo, float hi) {
    uint32_t r;                        // first src -> upper half
    asm("cvt.rn.bf16x2.f32 %0, %1, %2;" : "=r"(r) : "f"(hi), "f"(lo));
    return r;
}
__device__ __forceinline__ uint32_t pack_f16x2(float lo, float hi) {
    uint32_t r;                        // first src -> upper half
    asm("cvt.rn.f16x2.f32 %0, %1, %2;" : "=r"(r) : "f"(hi), "f"(lo));
    return r;
}
__device__ __forceinline__ uint32_t tanh_f16x2(uint32_t x) {
    uint32_t r;
    asm("tanh.approx.f16x2 %0, %1;" : "=r"(r) : "r"(x));
    return r;
}
__device__ __forceinline__ uint32_t fma_f16x2(uint32_t a, uint32_t b, uint32_t c) {
    uint32_t r;
    asm("fma.rn.f16x2 %0, %1, %2, %3;" : "=r"(r) : "r"(a), "r"(b), "r"(c));
    return r;
}
__device__ __forceinline__ void unpack_f16x2(uint32_t v, float& lo, float& hi) {
    asm("{ .reg .b16 l, h; mov.b32 {l, h}, %2; cvt.f32.f16 %0, l; cvt.f32.f16 %1, h; }"
        : "=f"(lo), "=f"(hi) : "r"(v));
}
__device__ __forceinline__ float tanh_hw(float x) {
    float r;
    asm("tanh.approx.f32 %0, %1;" : "=f"(r) : "f"(x));
    return r;
}
__device__ __forceinline__ void mma_bf16(float* d, const uint32_t* a,
                                         const uint32_t* b) {
    asm volatile(
        "mma.sync.aligned.m16n8k16.row.col.f32.bf16.bf16.f32 "
        "{%0,%1,%2,%3}, {%4,%5,%6,%7}, {%8,%9}, {%0,%1,%2,%3};"
        : "+f"(d[0]), "+f"(d[1]), "+f"(d[2]), "+f"(d[3])
        : "r"(a[0]), "r"(a[1]), "r"(a[2]), "r"(a[3]), "r"(b[0]), "r"(b[1]));
}

__global__ __launch_bounds__(128, 4)
void lstm_bf16p_kernel(const float* __restrict__ x,      // [B,T]
                       const float* __restrict__ W_ih,   // [4H]
                       const float* __restrict__ W_hh,   // [4H,H]
                       const float* __restrict__ b_ih,   // [4H]
                       const float* __restrict__ b_hh,   // [4H]
                       const float* __restrict__ fc_w,   // [H]
                       const float* __restrict__ fc_b,   // [1]
                       float* __restrict__ out)          // [B]
{
    __shared__ __align__(16) uint32_t hbuf[2][128];    // bf16x2, permuted
    __shared__ __align__(16) float    xs[XCH * NB];    // x chunk [t][n]

    const int tid = threadIdx.x;
    const int w   = tid >> 5;
    const int l   = tid & 31;
    const int gid = l >> 2;            // 0..7
    const int lq  = l & 3;             // 0..3
    const int b0  = blockIdx.x * NB;
    const int j   = 8 * w + gid;       // hidden unit owned in epilogue

    // A fragments (persistent, bf16); sigmoid gates (0,1,3) pre-scaled x0.5.
    uint32_t af[2][2][4];
    #pragma unroll
    for (int mt = 0; mt < 2; mt++) {
        const int g0 = 2 * mt, g1 = 2 * mt + 1;
        const float s0 = (g0 == 2) ? 1.0f : 0.5f;
        const float s1 = (g1 == 2) ? 1.0f : 0.5f;
        const float* r0 = W_hh + (g0 * HH + j) * HH;
        const float* r1 = W_hh + (g1 * HH + j) * HH;
        #pragma unroll
        for (int kt = 0; kt < 2; kt++) {
            const int k0 = kt * 16 + 2 * lq;
            af[mt][kt][0] = pack_bf16(r0[k0] * s0,     r0[k0 + 1] * s0);
            af[mt][kt][1] = pack_bf16(r1[k0] * s1,     r1[k0 + 1] * s1);
            af[mt][kt][2] = pack_bf16(r0[k0 + 8] * s0, r0[k0 + 9] * s0);
            af[mt][kt][3] = pack_bf16(r1[k0 + 8] * s1, r1[k0 + 9] * s1);
        }
    }

    float wih[4], bias[4];
    #pragma unroll
    for (int g = 0; g < 4; g++) {
        const float sc = (g == 2) ? 1.0f : 0.5f;
        wih[g]  = W_ih[g * HH + j] * sc;
        bias[g] = (b_ih[g * HH + j] + b_hh[g * HH + j]) * sc;
    }

    if (tid < 128) hbuf[0][tid] = 0u;

    const uint32_t* bfp[2] = { &hbuf[0][lq * 16 + gid * 2],
                               &hbuf[1][lq * 16 + gid * 2] };
    const int stw = (j >> 4) * 64 + ((j >> 1) & 3) * 16 + (2 * lq) * 2 + ((j >> 3) & 1);
    const int sth = (j & 1);
    uint16_t* stp[2] = {
        reinterpret_cast<uint16_t*>(&hbuf[0][stw]) + sth,
        reinterpret_cast<uint16_t*>(&hbuf[1][stw]) + sth };

    float c0 = 0.0f, c1 = 0.0f;
    const uint32_t H2 = 0x38003800u;   // (0.5, 0.5) in f16x2

    #pragma unroll 1
    for (int tb = 0; tb < TT; tb += 2) {
        if ((tb & (XCH - 1)) == 0) {
            const int n = tid >> 4, part = tid & 15;
            const float4 v = *reinterpret_cast<const float4*>(
                x + (size_t)(b0 + n) * TT + tb + part * 4);
            xs[(part * 4 + 0) * NB + n] = v.x;
            xs[(part * 4 + 1) * NB + n] = v.y;
            xs[(part * 4 + 2) * NB + n] = v.z;
            xs[(part * 4 + 3) * NB + n] = v.w;
            __syncthreads();
        }

        #pragma unroll
        for (int ph = 0; ph < 2; ph++) {
            const int t = tb + ph;
            const int p = ph;                  // tb even -> parity == ph

            const float2 xv = *reinterpret_cast<const float2*>(
                &xs[(t & (XCH - 1)) * NB + 2 * lq]);
            float acc[2][4];
            #pragma unroll
            for (int mt = 0; mt < 2; mt++) {
                acc[mt][0] = fmaf(xv.x, wih[2 * mt],     bias[2 * mt]);
                acc[mt][1] = fmaf(xv.y, wih[2 * mt],     bias[2 * mt]);
                acc[mt][2] = fmaf(xv.x, wih[2 * mt + 1], bias[2 * mt + 1]);
                acc[mt][3] = fmaf(xv.y, wih[2 * mt + 1], bias[2 * mt + 1]);
            }

            uint32_t bf[2][2];
            #pragma unroll
            for (int kt = 0; kt < 2; kt++) {
                const u64 v = *reinterpret_cast<const u64*>(bfp[p] + kt * 64);
                bf[kt][0] = (uint32_t)v;
                bf[kt][1] = (uint32_t)(v >> 32);
            }

            #pragma unroll
            for (int mt = 0; mt < 2; mt++) {
                mma_bf16(acc[mt], af[mt][0], bf[0]);
                mma_bf16(acc[mt], af[mt][1], bf[1]);
            }

            // --- epilogue: both cells together ---
            // sigmoid gates via ONE tanh.approx.f16x2 per gate-pair
            const uint32_t si = fma_f16x2(tanh_f16x2(pack_f16x2(acc[0][0], acc[0][1])), H2, H2);
            const uint32_t sf = fma_f16x2(tanh_f16x2(pack_f16x2(acc[0][2], acc[0][3])), H2, H2);
            const uint32_t so = fma_f16x2(tanh_f16x2(pack_f16x2(acc[1][2], acc[1][3])), H2, H2);
            // g-gate (feeds c directly) stays fp32
            const float gg0 = tanh_hw(acc[1][0]);
            const float gg1 = tanh_hw(acc[1][1]);
            float gi0, gi1, gf0, gf1, go0, go1;
            unpack_f16x2(si, gi0, gi1);
            unpack_f16x2(sf, gf0, gf1);
            unpack_f16x2(so, go0, go1);

            c0 = fmaf(gf0, c0, gi0 * gg0);
            c1 = fmaf(gf1, c1, gi1 * gg1);
            const float h0 = go0 * tanh_hw(c0);
            const float h1 = go1 * tanh_hw(c1);

            __nv_bfloat16 hb0 = __float2bfloat16(h0);
            __nv_bfloat16 hb1 = __float2bfloat16(h1);
            stp[p ^ 1][0] = *reinterpret_cast<uint16_t*>(&hb0);
            stp[p ^ 1][4] = *reinterpret_cast<uint16_t*>(&hb1);

            __syncthreads();
        }
    }

    // out[n] = dot(h[n,:], fc_w) + fc_b   (final h in hbuf[0]: T even)
    if (tid < NB) {
        const int n = tid;
        const uint16_t* hb16 = reinterpret_cast<const uint16_t*>(hbuf[0]);
        float s = fc_b[0];
        #pragma unroll
        for (int k = 0; k < HH; k++) {
            const int word = (k >> 4) * 64 + ((k >> 1) & 3) * 16 + n * 2 + ((k >> 3) & 1);
            const uint16_t bits = hb16[word * 2 + (k & 1)];
            __nv_bfloat16 hv = *reinterpret_cast<const __nv_bfloat16*>(&bits);
            s = fmaf(__bfloat162float(hv), fc_w[k], s);
        }
        out[b0 + n] = s;
    }
}

extern "C" void kernel_launch(void* const* d_in, const int* in_sizes, int n_in,
                              void* d_out, int out_size) {
    const float* x    = (const float*)d_in[0];
    const float* W_ih = (const float*)d_in[1];
    const float* W_hh = (const float*)d_in[2];
    const float* b_ih = (const float*)d_in[3];
    const float* b_hh = (const float*)d_in[4];
    const float* fc_w = (const float*)d_in[5];
    const float* fc_b = (const float*)d_in[6];
    float* out = (float*)d_out;

    lstm_bf16p_kernel<<<BB / NB, 128>>>(x, W_ih, W_hh, b_ih, b_hh, fc_w, fc_b, out);
}